// round 9
// baseline (speedup 1.0000x reference)
#include <cuda_runtime.h>
#include <cuda_bf16.h>

#define N_NODES 768
#define NF 128
#define MF 256
#define GF 256
#define TOT_NN (N_NODES * NF)          // 98304
#define EDGE_ELEMS (N_NODES * N_NODES) // 589824

// ---- scratch (device globals; no allocation) ----
__device__ float g_msg[N_NODES * MF];            // msg = nodes @ we
__device__ float g_psx[3][N_NODES * MF];         // partial sum(x)
__device__ float g_psa[3][N_NODES * MF];         // partial sum(|x|)
__device__ float g_pre[TOT_NN];                  // pre-norm new_nodes
__device__ float g_colsum[NF];
__device__ float g_stats[2];                     // {sum, sumsq}

// ---- packed f32x2 helpers (Blackwell-only; FFMA2 unreachable from C++) ----
__device__ __forceinline__ unsigned long long ffma2(unsigned long long a,
                                                    unsigned long long b,
                                                    unsigned long long c) {
    unsigned long long d;
    asm("fma.rn.f32x2 %0, %1, %2, %3;" : "=l"(d) : "l"(a), "l"(b), "l"(c));
    return d;
}
__device__ __forceinline__ unsigned long long fadd2(unsigned long long a,
                                                    unsigned long long b) {
    unsigned long long d;
    asm("add.rn.f32x2 %0, %1, %2;" : "=l"(d) : "l"(a), "l"(b));
    return d;
}
__device__ __forceinline__ unsigned long long dup2(float x) {
    unsigned long long d;
    asm("mov.b64 %0, {%1, %1};" : "=l"(d) : "f"(x));
    return d;
}
__device__ __forceinline__ void st_cs_u64(unsigned long long* p, unsigned long long v) {
    asm volatile("st.global.cs.b64 [%0], %1;" :: "l"(p), "l"(v) : "memory");
}

// ============================================================
// K1: msg[i,k] = sum_c nodes[i,c] * we[c,k]   (96 blocks x 256 thr, 8 rows/blk)
//     + zero the small atomic scratch (block 0) — must re-zero every replay
// ============================================================
__global__ __launch_bounds__(256) void k1_msg(const float* __restrict__ nodes,
                                              const float* __restrict__ we) {
    __shared__ __align__(16) float ns[8][NF];
    const int i0 = blockIdx.x * 8;
    if (blockIdx.x == 0) {
        if (threadIdx.x < NF) g_colsum[threadIdx.x] = 0.f;
        if (threadIdx.x < 2)  g_stats[threadIdx.x] = 0.f;
    }
    // 8*NF = 1024 floats = 256 float4; one LDG.128 per thread.
    reinterpret_cast<float4*>(&ns[0][0])[threadIdx.x] =
        reinterpret_cast<const float4*>(nodes + i0 * NF)[threadIdx.x];
    __syncthreads();

    const int k = threadIdx.x;
    float acc[8];
#pragma unroll
    for (int r = 0; r < 8; r++) acc[r] = 0.f;
#pragma unroll 8
    for (int c = 0; c < NF; c++) {
        const float w = we[c * MF + k];
#pragma unroll
        for (int r = 0; r < 8; r++) acc[r] = fmaf(ns[r][c], w, acc[r]);
    }
#pragma unroll
    for (int r = 0; r < 8; r++) g_msg[(i0 + r) * MF + k] = acc[r];
}

// ============================================================
// K2 (HOT): partial ebar sums, f32x2-packed over k.
// Grid (96, 3): x = i-tile (8 rows), y = j-chunk (256 j). 128 threads own 256 k.
// leaky_relu(x) = 0.505*x + 0.495*|x|  ->  accumulate sx = sum x, sa = sum |x|.
// Per pair: 1 FFMA2 + 2 ADD2 (fma pipe) + 64-bit AND (alu pipe).
// j processed 2 at a time: one LDS.128 fetches both duplicated edge values.
// ============================================================
__global__ __launch_bounds__(128) void k2_main(const float* __restrict__ edges,
                                               const float* __restrict__ b) {
    __shared__ __align__(16) unsigned long long es2[8][256]; // edge dup'd in both halves
    const int i0 = blockIdx.x * 8;
    const int j0 = blockIdx.y * 256;
    const int t  = threadIdx.x;                  // 0..127, owns k = {2t, 2t+1}

    // Tile fill: 8 rows x 64 float4 = 512 float4 by 128 threads (4 each, LDG.128).
    // Row base (i0+r)*768 + j0 is 16B-aligned (j0 % 256 == 0).
#pragma unroll
    for (int v = t; v < 512; v += 128) {
        const int r = v >> 6, q = v & 63;        // q: float4 index within row
        const float4 e4 = reinterpret_cast<const float4*>(
            edges + (i0 + r) * N_NODES + j0)[q];
        es2[r][q * 4 + 0] = dup2(e4.x);
        es2[r][q * 4 + 1] = dup2(e4.y);
        es2[r][q * 4 + 2] = dup2(e4.z);
        es2[r][q * 4 + 3] = dup2(e4.w);
    }
    __syncthreads();

    const unsigned long long bk2 =
        *reinterpret_cast<const unsigned long long*>(b + 2 * t);
    const unsigned long long* __restrict__ msg2 =
        reinterpret_cast<const unsigned long long*>(g_msg) + t;   // + j*(MF/2)

    unsigned long long sx[8], sa[8];
#pragma unroll
    for (int r = 0; r < 8; r++) { sx[r] = 0ull; sa[r] = 0ull; }

    const unsigned long long ABSM = 0x7FFFFFFF7FFFFFFFULL;
#pragma unroll 4
    for (int j = 0; j < 256; j += 2) {
        // __ldg: read-only non-coherent path; g_msg is not written after K1,
        // and the asm "memory" clobbers on the epilogue stores otherwise block
        // the compiler from proving read-only-ness.
        const unsigned long long m0 = __ldg(msg2 + (unsigned)(j0 + j)     * (MF / 2));
        const unsigned long long m1 = __ldg(msg2 + (unsigned)(j0 + j + 1) * (MF / 2));
#pragma unroll
        for (int r = 0; r < 8; r++) {
            const ulonglong2 e2 =
                *reinterpret_cast<const ulonglong2*>(&es2[r][j]);  // LDS.128 bcast
            const unsigned long long x0 = ffma2(m0, e2.x, bk2);
            sx[r] = fadd2(sx[r], x0);
            sa[r] = fadd2(sa[r], x0 & ABSM);
            const unsigned long long x1 = ffma2(m1, e2.y, bk2);
            sx[r] = fadd2(sx[r], x1);
            sa[r] = fadd2(sa[r], x1 & ABSM);
        }
    }

    const int jc = blockIdx.y;
#pragma unroll
    for (int r = 0; r < 8; r++) {
        const int off = ((i0 + r) * MF) / 2 + t;
        st_cs_u64(reinterpret_cast<unsigned long long*>(g_psx[jc]) + off, sx[r]);
        st_cs_u64(reinterpret_cast<unsigned long long*>(g_psa[jc]) + off, sa[r]);
    }
}

// ============================================================
// K3: ebar = 0.505*sx + 0.495*sa (combine 3 partials, float4-vectorized);
//     pre = lrelu(ebar @ wv) + nodes; accumulate sum/sumsq/colsum.
//     Grid: 96 blocks x 128 threads, 8 rows each.
// ============================================================
__global__ __launch_bounds__(128) void k3_update(const float* __restrict__ wv,
                                                 const float* __restrict__ nodes) {
    __shared__ __align__(16) float eb[8][MF];
    const int i0 = blockIdx.x * 8;

    // 8*MF = 2048 floats = 512 float4; tile base offset i0*MF is 16B-aligned.
    {
        const float4* px0 = reinterpret_cast<const float4*>(g_psx[0] + i0 * MF);
        const float4* px1 = reinterpret_cast<const float4*>(g_psx[1] + i0 * MF);
        const float4* px2 = reinterpret_cast<const float4*>(g_psx[2] + i0 * MF);
        const float4* pa0 = reinterpret_cast<const float4*>(g_psa[0] + i0 * MF);
        const float4* pa1 = reinterpret_cast<const float4*>(g_psa[1] + i0 * MF);
        const float4* pa2 = reinterpret_cast<const float4*>(g_psa[2] + i0 * MF);
        float4* ebv = reinterpret_cast<float4*>(&eb[0][0]);
#pragma unroll
        for (int v = threadIdx.x; v < 512; v += 128) {
            const float4 x0 = px0[v], x1 = px1[v], x2 = px2[v];
            const float4 a0 = pa0[v], a1 = pa1[v], a2 = pa2[v];
            float4 o;
            o.x = 0.505f * (x0.x + x1.x + x2.x) + 0.495f * (a0.x + a1.x + a2.x);
            o.y = 0.505f * (x0.y + x1.y + x2.y) + 0.495f * (a0.y + a1.y + a2.y);
            o.z = 0.505f * (x0.z + x1.z + x2.z) + 0.495f * (a0.z + a1.z + a2.z);
            o.w = 0.505f * (x0.w + x1.w + x2.w) + 0.495f * (a0.w + a1.w + a2.w);
            ebv[v] = o;
        }
    }
    __syncthreads();

    const int nf = threadIdx.x;
    float acc[8];
#pragma unroll
    for (int r = 0; r < 8; r++) acc[r] = 0.f;
#pragma unroll 8
    for (int c = 0; c < MF; c++) {
        const float w = wv[c * NF + nf];
#pragma unroll
        for (int r = 0; r < 8; r++) acc[r] = fmaf(eb[r][c], w, acc[r]);
    }

    float lsum = 0.f, lsq = 0.f;
#pragma unroll
    for (int r = 0; r < 8; r++) {
        const float x = acc[r];
        const float y = 0.505f * x + 0.495f * fabsf(x) + nodes[(i0 + r) * NF + nf];
        g_pre[(i0 + r) * NF + nf] = y;
        lsum += y;
        lsq  = fmaf(y, y, lsq);
    }
    atomicAdd(&g_colsum[nf], lsum);

    __shared__ float red0[128], red1[128];
    red0[nf] = lsum; red1[nf] = lsq;
    __syncthreads();
    for (int s = 64; s > 0; s >>= 1) {
        if (nf < s) { red0[nf] += red0[nf + s]; red1[nf] += red1[nf + s]; }
        __syncthreads();
    }
    if (nf == 0) {
        atomicAdd(&g_stats[0], red0[0]);
        atomicAdd(&g_stats[1], red1[0]);
    }
}

// ============================================================
// K4 (fused epilogue): depends only on K3's completed stats.
//   blocks [0, 96)        : LayerNorm (float4) -> d_out[0 : 98304]
//   blocks [96, 96+576)   : edges float4 copy -> d_out[98304 : +589824]
//   block  672            : new_features -> d_out[98304+589824 : +256]
// ============================================================
__global__ __launch_bounds__(256) void k4_epilogue(const float* __restrict__ edges,
                                                   const float* __restrict__ wu,
                                                   const float* __restrict__ features,
                                                   float* __restrict__ out) {
    const int bid = blockIdx.x;
    if (bid < 96) {
        const int idx = bid * 256 + threadIdx.x;           // float4 index < 24576
        const float inv_n = 1.f / (float)TOT_NN;
        const float mu  = g_stats[0] * inv_n;
        const float var = g_stats[1] * inv_n - mu * mu;
        const float inv = rsqrtf(var + 1e-5f);
        float4 v = __ldcs(reinterpret_cast<const float4*>(g_pre) + idx); // 1-use data
        v.x = (v.x - mu) * inv;
        v.y = (v.y - mu) * inv;
        v.z = (v.z - mu) * inv;
        v.w = (v.w - mu) * inv;
        __stcs(reinterpret_cast<float4*>(out) + idx, v);
    } else if (bid < 96 + 576) {
        const int idx = (bid - 96) * 256 + threadIdx.x;    // < 147456 float4
        // Pure streaming copy: evict-first both directions, keep L2 for the
        // norm branch running concurrently in other blocks.
        __stcs(reinterpret_cast<float4*>(out + TOT_NN) + idx,
               __ldcs(reinterpret_cast<const float4*>(edges) + idx));
    } else {
        __shared__ float gn[NF];
        const float inv_n = 1.f / (float)TOT_NN;
        const float mu  = g_stats[0] * inv_n;
        const float var = g_stats[1] * inv_n - mu * mu;
        const float inv = rsqrtf(var + 1e-5f);
        if (threadIdx.x < NF)
            gn[threadIdx.x] = (g_colsum[threadIdx.x] - (float)N_NODES * mu) * inv;
        __syncthreads();

        const int g = threadIdx.x;
        float acc = 0.f;
#pragma unroll 8
        for (int c = 0; c < NF; c++) acc = fmaf(gn[c], wu[c * GF + g], acc);
        const float y = 0.505f * acc + 0.495f * fabsf(acc) + features[g];
        out[TOT_NN + EDGE_ELEMS + g] = y;
    }
}

extern "C" void kernel_launch(void* const* d_in, const int* in_sizes, int n_in,
                              void* d_out, int out_size) {
    const float* nodes    = (const float*)d_in[0];
    const float* edges    = (const float*)d_in[1];
    const float* features = (const float*)d_in[2];
    const float* we       = (const float*)d_in[3];
    const float* b        = (const float*)d_in[4];
    const float* wv       = (const float*)d_in[5];
    const float* wu       = (const float*)d_in[6];
    float* out = (float*)d_out;

    k1_msg<<<96, 256>>>(nodes, we);
    dim3 g2(96, 3);
    k2_main<<<g2, 128>>>(edges, b);
    k3_update<<<96, 128>>>(wv, nodes);
    k4_epilogue<<<96 + 576 + 1, 256>>>(edges, wu, features, out);
}

// round 11
// speedup vs baseline: 1.4802x; 1.4802x over previous
#include <cuda_runtime.h>
#include <cuda_bf16.h>

#define N_NODES 768
#define NF 128
#define MF 256
#define GF 256
#define TOT_NN (N_NODES * NF)          // 98304
#define EDGE_ELEMS (N_NODES * N_NODES) // 589824
#define JCHUNKS 6
#define JTILE 128                      // 768 / 6

// ---- scratch (device globals; no allocation) ----
__device__ float g_msg[N_NODES * MF];            // msg = nodes @ we
__device__ float g_psx[JCHUNKS][N_NODES * MF];   // partial sum(x)
__device__ float g_psa[JCHUNKS][N_NODES * MF];   // partial sum(|x|)
__device__ float g_pre[TOT_NN];                  // pre-norm new_nodes
__device__ float g_colsum[NF];
__device__ float g_stats[2];                     // {sum, sumsq}

// ---- packed f32x2 helpers (Blackwell-only; FFMA2 unreachable from C++) ----
__device__ __forceinline__ unsigned long long ffma2(unsigned long long a,
                                                    unsigned long long b,
                                                    unsigned long long c) {
    unsigned long long d;
    asm("fma.rn.f32x2 %0, %1, %2, %3;" : "=l"(d) : "l"(a), "l"(b), "l"(c));
    return d;
}
__device__ __forceinline__ unsigned long long fadd2(unsigned long long a,
                                                    unsigned long long b) {
    unsigned long long d;
    asm("add.rn.f32x2 %0, %1, %2;" : "=l"(d) : "l"(a), "l"(b));
    return d;
}
__device__ __forceinline__ unsigned long long dup2(float x) {
    unsigned long long d;
    asm("mov.b64 %0, {%1, %1};" : "=l"(d) : "f"(x));
    return d;
}
__device__ __forceinline__ void st_cs_u64(unsigned long long* p, unsigned long long v) {
    asm volatile("st.global.cs.b64 [%0], %1;" :: "l"(p), "l"(v) : "memory");
}

// ============================================================
// K1: msg[i,k] = sum_c nodes[i,c] * we[c,k]   (96 blocks x 256 thr, 8 rows/blk)
//     + zero the small atomic scratch (block 0) — must re-zero every replay
// ============================================================
__global__ __launch_bounds__(256) void k1_msg(const float* __restrict__ nodes,
                                              const float* __restrict__ we) {
    __shared__ __align__(16) float ns[8][NF];
    const int i0 = blockIdx.x * 8;
    if (blockIdx.x == 0) {
        if (threadIdx.x < NF) g_colsum[threadIdx.x] = 0.f;
        if (threadIdx.x < 2)  g_stats[threadIdx.x] = 0.f;
    }
    reinterpret_cast<float4*>(&ns[0][0])[threadIdx.x] =
        reinterpret_cast<const float4*>(nodes + i0 * NF)[threadIdx.x];
    __syncthreads();

    const int k = threadIdx.x;
    float acc[8];
#pragma unroll
    for (int r = 0; r < 8; r++) acc[r] = 0.f;
#pragma unroll 8
    for (int c = 0; c < NF; c++) {
        const float w = we[c * MF + k];
#pragma unroll
        for (int r = 0; r < 8; r++) acc[r] = fmaf(ns[r][c], w, acc[r]);
    }
#pragma unroll
    for (int r = 0; r < 8; r++) g_msg[(i0 + r) * MF + k] = acc[r];
}

// ============================================================
// K2 (HOT): partial ebar sums, f32x2-packed over k.
// Grid (96, 6): x = i-tile (8 rows), y = j-chunk (128 j). 128 threads own 256 k.
// 4 blocks/SM -> 4 warps/SMSP for latency tolerance.
// leaky_relu(x) = 0.505*x + 0.495*|x| -> accumulate sx = sum x, sa = sum |x|.
// msg loads are software-pipelined one iteration ahead (wrap-indexed) so >=2
// independent LDG.64 are always in flight per warp.
// Tile fill ALSO streams the edges tile to d_out (each element covered once
// across the grid) — removes the latency-bound copy kernel entirely.
// ============================================================
__global__ __launch_bounds__(128) void k2_main(const float* __restrict__ edges,
                                               const float* __restrict__ b,
                                               float* __restrict__ out) {
    __shared__ __align__(16) unsigned long long es2[8][JTILE];
    const int i0 = blockIdx.x * 8;
    const int j0 = blockIdx.y * JTILE;
    const int t  = threadIdx.x;                  // 0..127, owns k = {2t, 2t+1}

    // Fill: 8 rows x 32 float4 = 256 float4; 2 per thread (LDG.128),
    // plus pass-through STG.128 of the same data into d_out's edges region.
#pragma unroll
    for (int v = t; v < 256; v += 128) {
        const int r = v >> 5, q = v & 31;        // q: float4 index within row
        const int rowbase = (i0 + r) * N_NODES + j0;
        const float4 e4 =
            reinterpret_cast<const float4*>(edges + rowbase)[q];
        es2[r][q * 4 + 0] = dup2(e4.x);
        es2[r][q * 4 + 1] = dup2(e4.y);
        es2[r][q * 4 + 2] = dup2(e4.z);
        es2[r][q * 4 + 3] = dup2(e4.w);
        reinterpret_cast<float4*>(out + TOT_NN + rowbase)[q] = e4;
    }
    __syncthreads();

    const unsigned long long bk2 =
        *reinterpret_cast<const unsigned long long*>(b + 2 * t);
    const unsigned long long* __restrict__ msg2 =
        reinterpret_cast<const unsigned long long*>(g_msg) + t;   // + j*(MF/2)

    unsigned long long sx[8], sa[8];
#pragma unroll
    for (int r = 0; r < 8; r++) { sx[r] = 0ull; sa[r] = 0ull; }

    const unsigned long long ABSM = 0x7FFFFFFF7FFFFFFFULL;

    // Software pipeline: load pair for j, prefetch pair for j+2 (wrap at end).
    unsigned long long m0 = __ldg(msg2 + (unsigned)(j0 + 0) * (MF / 2));
    unsigned long long m1 = __ldg(msg2 + (unsigned)(j0 + 1) * (MF / 2));
#pragma unroll 4
    for (int j = 0; j < JTILE; j += 2) {
        const int jn = (j + 2) & (JTILE - 1);    // wraps to 0 on last iter
        const unsigned long long n0 = __ldg(msg2 + (unsigned)(j0 + jn)     * (MF / 2));
        const unsigned long long n1 = __ldg(msg2 + (unsigned)(j0 + jn + 1) * (MF / 2));
#pragma unroll
        for (int r = 0; r < 8; r++) {
            const ulonglong2 e2 =
                *reinterpret_cast<const ulonglong2*>(&es2[r][j]);  // LDS.128 bcast
            const unsigned long long x0 = ffma2(m0, e2.x, bk2);
            sx[r] = fadd2(sx[r], x0);
            sa[r] = fadd2(sa[r], x0 & ABSM);
            const unsigned long long x1 = ffma2(m1, e2.y, bk2);
            sx[r] = fadd2(sx[r], x1);
            sa[r] = fadd2(sa[r], x1 & ABSM);
        }
        m0 = n0;
        m1 = n1;
    }

    const int jc = blockIdx.y;
#pragma unroll
    for (int r = 0; r < 8; r++) {
        const int off = ((i0 + r) * MF) / 2 + t;
        st_cs_u64(reinterpret_cast<unsigned long long*>(g_psx[jc]) + off, sx[r]);
        st_cs_u64(reinterpret_cast<unsigned long long*>(g_psa[jc]) + off, sa[r]);
    }
}

// ============================================================
// K3: ebar = 0.505*sx + 0.495*sa (combine 6 partials, float4-vectorized);
//     pre = lrelu(ebar @ wv) + nodes; accumulate sum/sumsq/colsum.
//     Grid: 96 blocks x 128 threads, 8 rows each.
// ============================================================
__global__ __launch_bounds__(128) void k3_update(const float* __restrict__ wv,
                                                 const float* __restrict__ nodes) {
    __shared__ __align__(16) float eb[8][MF];
    const int i0 = blockIdx.x * 8;

    // 8*MF = 2048 floats = 512 float4; tile base offset i0*MF is 16B-aligned.
    {
        float4* ebv = reinterpret_cast<float4*>(&eb[0][0]);
#pragma unroll
        for (int v = threadIdx.x; v < 512; v += 128) {
            float sxx = 0.f, sxy = 0.f, sxz = 0.f, sxw = 0.f;
            float sax = 0.f, say = 0.f, saz = 0.f, saw = 0.f;
#pragma unroll
            for (int c = 0; c < JCHUNKS; c++) {
                const float4 x = reinterpret_cast<const float4*>(g_psx[c] + i0 * MF)[v];
                const float4 a = reinterpret_cast<const float4*>(g_psa[c] + i0 * MF)[v];
                sxx += x.x; sxy += x.y; sxz += x.z; sxw += x.w;
                sax += a.x; say += a.y; saz += a.z; saw += a.w;
            }
            float4 o;
            o.x = 0.505f * sxx + 0.495f * sax;
            o.y = 0.505f * sxy + 0.495f * say;
            o.z = 0.505f * sxz + 0.495f * saz;
            o.w = 0.505f * sxw + 0.495f * saw;
            ebv[v] = o;
        }
    }
    __syncthreads();

    const int nf = threadIdx.x;
    float acc[8];
#pragma unroll
    for (int r = 0; r < 8; r++) acc[r] = 0.f;
#pragma unroll 8
    for (int c = 0; c < MF; c++) {
        const float w = wv[c * NF + nf];
#pragma unroll
        for (int r = 0; r < 8; r++) acc[r] = fmaf(eb[r][c], w, acc[r]);
    }

    float lsum = 0.f, lsq = 0.f;
#pragma unroll
    for (int r = 0; r < 8; r++) {
        const float x = acc[r];
        const float y = 0.505f * x + 0.495f * fabsf(x) + nodes[(i0 + r) * NF + nf];
        g_pre[(i0 + r) * NF + nf] = y;
        lsum += y;
        lsq  = fmaf(y, y, lsq);
    }
    atomicAdd(&g_colsum[nf], lsum);

    __shared__ float red0[128], red1[128];
    red0[nf] = lsum; red1[nf] = lsq;
    __syncthreads();
    for (int s = 64; s > 0; s >>= 1) {
        if (nf < s) { red0[nf] += red0[nf + s]; red1[nf] += red1[nf + s]; }
        __syncthreads();
    }
    if (nf == 0) {
        atomicAdd(&g_stats[0], red0[0]);
        atomicAdd(&g_stats[1], red1[0]);
    }
}

// ============================================================
// K4 (epilogue, copy removed — it lives in K2 now):
//   blocks [0, 96) : LayerNorm (float4) -> d_out[0 : 98304]
//   block  96      : new_features -> d_out[98304+589824 : +256]
// One resident wave; ~2 us.
// ============================================================
__global__ __launch_bounds__(256) void k4_epilogue(const float* __restrict__ wu,
                                                   const float* __restrict__ features,
                                                   float* __restrict__ out) {
    const int bid = blockIdx.x;
    if (bid < 96) {
        const int idx = bid * 256 + threadIdx.x;           // float4 index < 24576
        const float inv_n = 1.f / (float)TOT_NN;
        const float mu  = g_stats[0] * inv_n;
        const float var = g_stats[1] * inv_n - mu * mu;
        const float inv = rsqrtf(var + 1e-5f);
        float4 v = __ldcs(reinterpret_cast<const float4*>(g_pre) + idx); // 1-use data
        v.x = (v.x - mu) * inv;
        v.y = (v.y - mu) * inv;
        v.z = (v.z - mu) * inv;
        v.w = (v.w - mu) * inv;
        __stcs(reinterpret_cast<float4*>(out) + idx, v);
    } else {
        __shared__ float gn[NF];
        const float inv_n = 1.f / (float)TOT_NN;
        const float mu  = g_stats[0] * inv_n;
        const float var = g_stats[1] * inv_n - mu * mu;
        const float inv = rsqrtf(var + 1e-5f);
        if (threadIdx.x < NF)
            gn[threadIdx.x] = (g_colsum[threadIdx.x] - (float)N_NODES * mu) * inv;
        __syncthreads();

        const int g = threadIdx.x;
        float acc = 0.f;
#pragma unroll 8
        for (int c = 0; c < NF; c++) acc = fmaf(gn[c], wu[c * GF + g], acc);
        const float y = 0.505f * acc + 0.495f * fabsf(acc) + features[g];
        out[TOT_NN + EDGE_ELEMS + g] = y;
    }
}

extern "C" void kernel_launch(void* const* d_in, const int* in_sizes, int n_in,
                              void* d_out, int out_size) {
    const float* nodes    = (const float*)d_in[0];
    const float* edges    = (const float*)d_in[1];
    const float* features = (const float*)d_in[2];
    const float* we       = (const float*)d_in[3];
    const float* b        = (const float*)d_in[4];
    const float* wv       = (const float*)d_in[5];
    const float* wu       = (const float*)d_in[6];
    float* out = (float*)d_out;

    k1_msg<<<96, 256>>>(nodes, we);
    dim3 g2(96, JCHUNKS);
    k2_main<<<g2, 128>>>(edges, b, out);
    k3_update<<<96, 128>>>(wv, nodes);
    k4_epilogue<<<96 + 1, 256>>>(wu, features, out);
}